// round 1
// baseline (speedup 1.0000x reference)
#include <cuda_runtime.h>
#include <math.h>

// ---------------- scratch (device globals: allowed; no allocs) ----------------
__device__ float g_c1 [4*256*128*128]; // conv1 out (raw, pre-relu)   64 MB
__device__ float g_c2 [4*128* 64* 64]; // conv2 out (raw)              8 MB
__device__ float g_c3 [4*128* 32* 32]; // conv3 out (raw)              2 MB
__device__ float g_lat[4*256*128*128]; // lat out (relu'd)            64 MB
__device__ float g_ow [4* 73*128*128]; // pred out (raw)              19 MB
__device__ float g_wt [4*144*64];      // dcn_w transposed [g][c*9+k][o]

// ---------------- generic 3x3 pad-1 conv as implicit GEMM ----------------
// M = COUT, N = B*OH*OW, K = CIN*9.  128x128 block tile, BK=8, 8x8 micro-tile.
// MODE 0: plain input p0 [B,CIN,IH,IW]
// MODE 1: concat(cur=p0, sup=p1), each [B,64,128,128]  (CIN=128)
// MODE 2: relu-concat( c1=p0 [B,256,128,128], up2(c2=p1 [B,128,64,64]),
//                      up4(c3=p2 [B,128,32,32]) )      (CIN=512)
template<int MODE, int CIN, int COUT, int STRIDE, int OH, int OW, bool RELU, bool HASBIAS>
__global__ __launch_bounds__(256)
void conv3x3_kernel(const float* __restrict__ p0,
                    const float* __restrict__ p1,
                    const float* __restrict__ p2,
                    const float* __restrict__ w,
                    const float* __restrict__ bias,
                    float* __restrict__ out)
{
    constexpr int K   = CIN * 9;
    constexpr int IH  = OH * STRIDE;
    constexpr int IW  = OW * STRIDE;
    constexpr int OHW = OH * OW;

    __shared__ float As[8][128];
    __shared__ float Bs[8][128];

    const int tid = threadIdx.x;
    const int m0  = blockIdx.y * 128;
    const int n0  = blockIdx.x * 128;

    // ---- B (im2col) gather setup: n fixed per thread ----
    const int nn    = tid & 127;
    const int kbase = tid >> 7;          // 0 or 1
    const int n     = n0 + nn;
    const int b     = n / OHW;           // power-of-two -> shift
    const int rem   = n - b * OHW;
    const int oy    = rem / OW;
    const int ox    = rem - oy * OW;
    const int iy0   = oy * STRIDE - 1;
    const int ix0   = ox * STRIDE - 1;

    // ---- A (weights) load setup ----
    const int am = tid >> 2;             // 0..63
    const int ak = (tid & 3) * 2;        // even k offset (float2)

    const int tx = tid & 15;
    const int ty = tid >> 4;

    float acc[8][8];
    #pragma unroll
    for (int i = 0; i < 8; i++)
        #pragma unroll
        for (int j = 0; j < 8; j++) acc[i][j] = 0.f;

    for (int k0 = 0; k0 < K; k0 += 8) {
        // load A: each thread 2 x float2 (k-contiguous in [COUT,CIN,3,3])
        #pragma unroll
        for (int h = 0; h < 2; h++) {
            int m = m0 + am + h * 64;
            float2 av = make_float2(0.f, 0.f);
            if (m < COUT) av = *(const float2*)(w + (size_t)m * K + k0 + ak);
            As[ak    ][am + h * 64] = av.x;
            As[ak + 1][am + h * 64] = av.y;
        }
        // load B: each thread 4 gathered values (same n, 4 k's)
        #pragma unroll
        for (int h = 0; h < 4; h++) {
            int k  = k0 + kbase + h * 2;
            int ci = k / 9;
            int rr = k - ci * 9;
            int ky = rr / 3;
            int kx = rr - ky * 3;
            int iy = iy0 + ky;
            int ix = ix0 + kx;
            float v = 0.f;
            if (iy >= 0 && iy < IH && ix >= 0 && ix < IW) {
                if (MODE == 0) {
                    v = p0[(((size_t)b * CIN + ci) * IH + iy) * IW + ix];
                } else if (MODE == 1) {
                    const float* p = (ci < 64) ? p0 : p1;
                    int c = ci & 63;
                    v = p[(((size_t)b * 64 + c) * 128 + iy) * 128 + ix];
                } else {
                    float t;
                    if (ci < 256)
                        t = p0[(((size_t)b * 256 + ci) * 128 + iy) * 128 + ix];
                    else if (ci < 384)
                        t = p1[(((size_t)b * 128 + (ci - 256)) * 64 + (iy >> 1)) * 64 + (ix >> 1)];
                    else
                        t = p2[(((size_t)b * 128 + (ci - 384)) * 32 + (iy >> 2)) * 32 + (ix >> 2)];
                    v = fmaxf(t, 0.f);
                }
            }
            Bs[kbase + h * 2][nn] = v;
        }
        __syncthreads();

        #pragma unroll
        for (int kq = 0; kq < 8; kq++) {
            float a[8], bb[8];
            *(float4*)&a[0]  = *(const float4*)&As[kq][ty * 4];
            *(float4*)&a[4]  = *(const float4*)&As[kq][64 + ty * 4];
            *(float4*)&bb[0] = *(const float4*)&Bs[kq][tx * 4];
            *(float4*)&bb[4] = *(const float4*)&Bs[kq][64 + tx * 4];
            #pragma unroll
            for (int i = 0; i < 8; i++)
                #pragma unroll
                for (int j = 0; j < 8; j++)
                    acc[i][j] = fmaf(a[i], bb[j], acc[i][j]);
        }
        __syncthreads();
    }

    // store
    #pragma unroll
    for (int i = 0; i < 8; i++) {
        int m = m0 + ((i < 4) ? (ty * 4 + i) : (64 + ty * 4 + i - 4));
        if (m >= COUT) continue;
        float bv = HASBIAS ? bias[m] : 0.f;
        #pragma unroll
        for (int j = 0; j < 8; j++) {
            int n2 = n0 + ((j < 4) ? (tx * 4 + j) : (64 + tx * 4 + j - 4));
            int b2 = n2 / OHW;
            int r2 = n2 - b2 * OHW;
            float v = acc[i][j] + bv;
            if (RELU) v = fmaxf(v, 0.f);
            out[((size_t)b2 * COUT + m) * OHW + r2] = v;
        }
    }
}

// ---------------- dcn weight transpose: [o][g*16+c][k] -> [g][c*9+k][o] ----------------
__global__ void transpose_dcn_w(const float* __restrict__ dcn_w, float* __restrict__ wt)
{
    int e = blockIdx.x * 256 + threadIdx.x;
    if (e >= 4 * 144 * 64) return;
    int o   = e & 63;
    int gck = e >> 6;
    int g   = gck / 144;
    int ck  = gck - g * 144;
    int c   = ck / 9;
    int k   = ck - c * 9;
    wt[e] = dcn_w[((size_t)(o * 64 + g * 16 + c)) * 9 + k];
}

// ---------------- deformable conv (dg=4, Cg=16, K=3) ----------------
// Block: 128 threads, 32 pixels. Stage bilinear samples per-g in smem,
// weights via __ldg float4 from g_wt (L1/L2 resident). 4px x 4o micro-tile.
__global__ __launch_bounds__(128)
void deform_kernel(const float* __restrict__ sup,
                   const float* __restrict__ ow,
                   const float* __restrict__ wt,
                   float* __restrict__ out)
{
    __shared__ float s[144 * 32];
    const int t  = threadIdx.x;
    const int p0 = blockIdx.x * 32;
    const int og = t & 15;   // o-group: o0 = og*4
    const int pg = t >> 4;   // px-group: px0 = pg*4

    float acc[4][4] = {};    // [px][o]

    for (int g = 0; g < 4; g++) {
        if (g) __syncthreads();   // prior compute must finish before s overwrite
        // ---- sampling: 288 tasks = 32 px * 9 k, lane-major in px ----
        for (int tt = t; tt < 288; tt += 128) {
            int px = tt & 31;
            int k  = tt >> 5;
            int p  = p0 + px;
            int b  = p >> 14;
            int yx = p & 16383;
            int yy = yx >> 7;
            int xx = yx & 127;
            int ky = k / 3;
            int kx = k - ky * 3;
            int och = (g * 9 + k) * 2;
            const float* owb = ow + ((size_t)b * 73 + och) * 16384 + yx;
            float dy = owb[0];
            float dx = owb[16384];
            float py  = (float)(yy + ky - 1) + dy;
            float pxf = (float)(xx + kx - 1) + dx;
            float y0f = floorf(py), x0f = floorf(pxf);
            int   y0  = (int)y0f,  x0  = (int)x0f;
            float wy1 = py  - y0f, wx1 = pxf - x0f;
            float wy0 = 1.f - wy1, wx0 = 1.f - wx1;
            bool vy0 = (unsigned)y0       < 128u;
            bool vy1 = (unsigned)(y0 + 1) < 128u;
            bool vx0 = (unsigned)x0       < 128u;
            bool vx1 = (unsigned)(x0 + 1) < 128u;
            float w00 = (vy0 && vx0) ? wy0 * wx0 : 0.f;
            float w01 = (vy0 && vx1) ? wy0 * wx1 : 0.f;
            float w10 = (vy1 && vx0) ? wy1 * wx0 : 0.f;
            float w11 = (vy1 && vx1) ? wy1 * wx1 : 0.f;
            int yc0 = min(max(y0, 0), 127);
            int yc1 = min(max(y0 + 1, 0), 127);
            int xc0 = min(max(x0, 0), 127);
            int xc1 = min(max(x0 + 1, 0), 127);
            const float* fb = sup + ((size_t)b * 64 + g * 16) * 16384;
            int i00 = yc0 * 128 + xc0, i01 = yc0 * 128 + xc1;
            int i10 = yc1 * 128 + xc0, i11 = yc1 * 128 + xc1;
            #pragma unroll
            for (int c = 0; c < 16; c++) {
                const float* f = fb + c * 16384;
                float v = w00 * f[i00] + w01 * f[i01] + w10 * f[i10] + w11 * f[i11];
                s[(c * 9 + k) * 32 + px] = v;     // bank = px -> conflict-free
            }
        }
        __syncthreads();
        // ---- accumulate: acc[px][o] += s[ck][px] * wt[g][ck][o] ----
        const float* wg = wt + g * 144 * 64;
        #pragma unroll 4
        for (int ck = 0; ck < 144; ck++) {
            float4 v4 = *(const float4*)&s[ck * 32 + pg * 4];
            float4 w4 = __ldg((const float4*)(wg + ck * 64 + og * 4));
            float v[4] = {v4.x, v4.y, v4.z, v4.w};
            float wv[4] = {w4.x, w4.y, w4.z, w4.w};
            #pragma unroll
            for (int i = 0; i < 4; i++)
                #pragma unroll
                for (int j = 0; j < 4; j++)
                    acc[i][j] = fmaf(v[i], wv[j], acc[i][j]);
        }
    }

    #pragma unroll
    for (int i = 0; i < 4; i++) {
        int p  = p0 + pg * 4 + i;
        int b  = p >> 14;
        int yx = p & 16383;
        #pragma unroll
        for (int j = 0; j < 4; j++) {
            int o = og * 4 + j;
            out[((size_t)b * 64 + o) * 16384 + yx] = acc[i][j];
        }
    }
}

// ---------------- weight channel: relu(ow[:,72]) ----------------
__global__ void weight_relu_kernel(const float* __restrict__ ow, float* __restrict__ out2)
{
    int i  = blockIdx.x * 256 + threadIdx.x;   // 65536
    int b  = i >> 14;
    int yx = i & 16383;
    out2[i] = fmaxf(ow[((size_t)b * 73 + 72) * 16384 + yx], 0.f);
}

// ---------------- launch ----------------
extern "C" void kernel_launch(void* const* d_in, const int* in_sizes, int n_in,
                              void* d_out, int out_size)
{
    const float* cur    = (const float*)d_in[0];
    const float* sup    = (const float*)d_in[1];
    // d_in[2] = idx (always 0 for this problem -> stride path)
    const float* off_w1 = (const float*)d_in[3];
    const float* off_w2 = (const float*)d_in[4];
    const float* off_w3 = (const float*)d_in[5];
    const float* lat_w  = (const float*)d_in[6];
    const float* lat_b  = (const float*)d_in[7];
    const float* pred_w = (const float*)d_in[8];
    const float* pred_b = (const float*)d_in[9];
    const float* dcn_w  = (const float*)d_in[10];
    float* out = (float*)d_out;

    float *c1, *c2, *c3, *lat, *owb, *wtb;
    cudaGetSymbolAddress((void**)&c1,  g_c1);
    cudaGetSymbolAddress((void**)&c2,  g_c2);
    cudaGetSymbolAddress((void**)&c3,  g_c3);
    cudaGetSymbolAddress((void**)&lat, g_lat);
    cudaGetSymbolAddress((void**)&owb, g_ow);
    cudaGetSymbolAddress((void**)&wtb, g_wt);

    // conv1: concat(cur,sup) [4,128,128,128] -> c1 [4,256,128,128]
    conv3x3_kernel<1,128,256,1,128,128,false,false>
        <<<dim3(512, 2), 256>>>(cur, sup, nullptr, off_w1, nullptr, c1);
    // conv2: c1 -> c2 [4,128,64,64], stride 2
    conv3x3_kernel<0,256,128,2,64,64,false,false>
        <<<dim3(128, 1), 256>>>(c1, nullptr, nullptr, off_w2, nullptr, c2);
    // conv3: c2 -> c3 [4,128,32,32], stride 2
    conv3x3_kernel<0,128,128,2,32,32,false,false>
        <<<dim3(32, 1), 256>>>(c2, nullptr, nullptr, off_w3, nullptr, c3);
    // lat: relu-concat(c1, up2(c2), up4(c3)) -> relu(conv+bias) [4,256,128,128]
    conv3x3_kernel<2,512,256,1,128,128,true,true>
        <<<dim3(512, 2), 256>>>(c1, c2, c3, lat_w, lat_b, lat);
    // pred: lat -> ow [4,73,128,128]
    conv3x3_kernel<0,256,73,1,128,128,false,true>
        <<<dim3(512, 1), 256>>>(lat, nullptr, nullptr, pred_w, pred_b, owb);

    transpose_dcn_w<<<144, 256>>>(dcn_w, wtb);
    deform_kernel<<<2048, 128>>>(sup, owb, wtb, out);
    weight_relu_kernel<<<256, 256>>>(owb, out + 4 * 64 * 128 * 128);
}

// round 9
// speedup vs baseline: 1.3052x; 1.3052x over previous
#include <cuda_runtime.h>
#include <cuda_bf16.h>
#include <math.h>
#include <stdint.h>

// R8->R9: bf16x6 products on tensor cores, but per-k16-tile DRAIN of the MMA
// accumulator into persistent fp32 registers via IEEE FADD. Rationale: R7
// (3xTF32) and R8 (bf16x6) hit an identical ~1.7e-3 error floor despite 32x
// input-precision difference => floor is the tensor-core internal accumulate
// rounding over K=4608, coherent bias, amplified by the offset->bilinear chain.
// Draining per tile confines TC rounding to 6 adds on small partials.

// ---------------- scratch (device globals: allowed; no allocs) ----------------
__device__ float g_c1 [4*256*128*128]; // conv1 out (raw)             64 MB
__device__ float g_c2 [4*128* 64* 64]; // conv2 out (raw)              8 MB
__device__ float g_c3 [4*128* 32* 32]; // conv3 out (raw)              2 MB
__device__ float g_lat[4*256*128*128]; // lat out (relu'd)            64 MB
__device__ float g_ow [4* 73*128*128]; // pred out (raw)              19 MB
__device__ float g_wt [4*144*64];      // dcn_w transposed [g][c*9+k][o]
__device__ float g_wT [2211840];       // conv weights: [k][m] padded fp32

// wT offsets (floats)
#define WT_C1   0          // 1152*256
#define WT_C2   294912     // 2304*128
#define WT_C3   589824     // 1152*128
#define WT_LAT  737280     // 4608*256
#define WT_PRED 1916928    // 2304*128

// 3-way bf16 split: v = s0 + s1 + s2, residual ~2^-27*|v|
__device__ __forceinline__ void split3(float v, unsigned short& s0,
                                       unsigned short& s1, unsigned short& s2)
{
    __nv_bfloat16 b0 = __float2bfloat16_rn(v);
    float r = v - __bfloat162float(b0);
    __nv_bfloat16 b1 = __float2bfloat16_rn(r);
    r -= __bfloat162float(b1);
    __nv_bfloat16 b2 = __float2bfloat16_rn(r);
    s0 = __bfloat16_as_ushort(b0);
    s1 = __bfloat16_as_ushort(b1);
    s2 = __bfloat16_as_ushort(b2);
}
__device__ __forceinline__ unsigned packu(unsigned short lo, unsigned short hi)
{
    return (unsigned)lo | ((unsigned)hi << 16);   // even k in low half
}

__device__ __forceinline__ void mma_bf16(float (&d)[4], const unsigned (&a)[4],
                                         const unsigned (&b)[2])
{
    asm volatile(
        "mma.sync.aligned.m16n8k16.row.col.f32.bf16.bf16.f32 "
        "{%0,%1,%2,%3},{%4,%5,%6,%7},{%8,%9},{%0,%1,%2,%3};"
        : "+f"(d[0]), "+f"(d[1]), "+f"(d[2]), "+f"(d[3])
        : "r"(a[0]), "r"(a[1]), "r"(a[2]), "r"(a[3]), "r"(b[0]), "r"(b[1]));
}

// ------------- weight prep: [COUT][K] -> [K][MP] (zero-padded fp32) -------------
__global__ void prep_w(const float* __restrict__ w, float* __restrict__ wT,
                       int K, int COUT, int MP)
{
    int idx = blockIdx.x * 256 + threadIdx.x;
    if (idx >= K * MP) return;
    int m = idx % MP;
    int k = idx / MP;
    wT[idx] = (m < COUT) ? w[(size_t)m * K + k] : 0.f;
}

// ---------------- bf16x6 tensor-core implicit-GEMM 3x3 conv ----------------
// M = COUT (pad MP), N = B*OH*OW, K = CIN*9. 128x128 tile, BK=16 (one k16 slab).
// 8 warps: warp tile 64x32 = 4x4 m16n8k16, 6 MMAs each into a zeroed temp,
// drained to fp32 regs per tile. Double-buffered smem, 3 bf16x2 planes/matrix.
// MODE 0: plain p0; MODE 1: concat(cur,sup); MODE 2: relu-concat(c1,up2(c2),up4(c3)).
template<int MODE, int CIN, int COUT, int MP, int STRIDE, int OH, int OW, bool RELU, bool HASBIAS>
__global__ __launch_bounds__(256, 2)
void conv3x3_bf(const float* __restrict__ p0, const float* __restrict__ p1,
                const float* __restrict__ p2, const float* __restrict__ wT,
                const float* __restrict__ bias, float* __restrict__ out)
{
    constexpr int K     = CIN * 9;
    constexpr int KT    = K / 16;
    constexpr int IH    = OH * STRIDE;
    constexpr int IW    = OW * STRIDE;
    constexpr int OHW   = OH * OW;
    constexpr int PR    = 136;          // pair-row stride (32-bit words)
    constexpr int PLANE = 8 * PR;       // 8 pair-rows per k16 slab

    extern __shared__ unsigned sm[];    // [buf][mat][plane][PLANE]

    const int tid  = threadIdx.x;
    const int lane = tid & 31;
    const int wid  = tid >> 5;
    const int l4   = lane & 3;
    const int l8   = lane >> 2;
    const int m0   = blockIdx.y * 128;
    const int n0   = blockIdx.x * 128;
    const int warp_m = (wid >> 2) * 64;
    const int warp_n = (wid & 3) * 32;

    auto Ab = [&](int buf, int p) { return sm + ((buf * 2 + 0) * 3 + p) * PLANE; };
    auto Bb = [&](int buf, int p) { return sm + ((buf * 2 + 1) * 3 + p) * PLANE; };

    // ---- B gather state (n fixed per thread; k advances incrementally) ----
    const int nn  = tid & 127;
    const int kk  = tid >> 7;               // 0/1 -> k base 8*kk within BK
    const int n   = n0 + nn;
    const int b   = n / OHW;                // pow2
    const int rem = n - b * OHW;
    const int oy  = rem / OW;
    const int ox  = rem - oy * OW;
    const int iy0 = oy * STRIDE - 1;
    const int ix0 = ox * STRIDE - 1;
    int ci0 = (kk * 8) / 9;                 // 0
    int rr0 = kk * 8 - ci0 * 9;             // 0 or 8

    float a0r[4], a1r[4];                   // A: k rows 2*wid, 2*wid+1; m = lane+32c
    float breg[8];

    float acc[4][4][4];
    #pragma unroll
    for (int i = 0; i < 4; i++)
        #pragma unroll
        for (int j = 0; j < 4; j++)
            #pragma unroll
            for (int r = 0; r < 4; r++) acc[i][j][r] = 0.f;

    auto gatherA = [&](int kt) {
        const float* p = wT + (size_t)(kt * 16 + 2 * wid) * MP + m0 + lane;
        #pragma unroll
        for (int c = 0; c < 4; c++) {
            a0r[c] = p[32 * c];
            a1r[c] = p[MP + 32 * c];
        }
    };

    auto gatherB = [&]() {
        #pragma unroll
        for (int h = 0; h < 8; h++) {
            int rr = rr0 + h, ci = ci0;
            if (rr >= 9) { rr -= 9; ci += 1; }
            int ky = (rr * 11) >> 5;        // rr/3 for rr<9
            int kx = rr - ky * 3;
            int iy = iy0 + ky;
            int ix = ix0 + kx;
            bool ok = ((unsigned)iy < (unsigned)IH) && ((unsigned)ix < (unsigned)IW);
            float v = 0.f;
            if (ok) {
                if (MODE == 0) {
                    v = p0[(((size_t)b * CIN + ci) * IH + iy) * IW + ix];
                } else if (MODE == 1) {
                    const float* p = (ci < 64) ? p0 : p1;
                    v = p[(((size_t)b * 64 + (ci & 63)) * 128 + iy) * 128 + ix];
                } else {
                    float t;
                    if (ci < 256)
                        t = p0[(((size_t)b * 256 + ci) * 128 + iy) * 128 + ix];
                    else if (ci < 384)
                        t = p1[(((size_t)b * 128 + (ci - 256)) * 64 + (iy >> 1)) * 64 + (ix >> 1)];
                    else
                        t = p2[(((size_t)b * 128 + (ci - 384)) * 32 + (iy >> 2)) * 32 + (ix >> 2)];
                    v = fmaxf(t, 0.f);
                }
            }
            breg[h] = v;
        }
        ci0 += 1; rr0 += 7;                 // advance k by 16
        if (rr0 >= 9) { rr0 -= 9; ci0 += 1; }
    };

    auto storeA = [&](int buf) {
        #pragma unroll
        for (int c = 0; c < 4; c++) {
            unsigned short e0, e1, e2, o0, o1, o2;
            split3(a0r[c], e0, e1, e2);     // even k (row 2*wid)
            split3(a1r[c], o0, o1, o2);     // odd  k (row 2*wid+1)
            unsigned idx = wid * PR + lane + 32 * c;
            Ab(buf, 0)[idx] = packu(e0, o0);
            Ab(buf, 1)[idx] = packu(e1, o1);
            Ab(buf, 2)[idx] = packu(e2, o2);
        }
    };

    auto storeB = [&](int buf) {
        #pragma unroll
        for (int t = 0; t < 4; t++) {
            unsigned short e0, e1, e2, o0, o1, o2;
            split3(breg[2 * t],     e0, e1, e2);
            split3(breg[2 * t + 1], o0, o1, o2);
            unsigned idx = (kk * 4 + t) * PR + nn;
            Bb(buf, 0)[idx] = packu(e0, o0);
            Bb(buf, 1)[idx] = packu(e1, o1);
            Bb(buf, 2)[idx] = packu(e2, o2);
        }
    };

    auto compute = [&](int buf) {
        unsigned bf[3][4][2];
        #pragma unroll
        for (int j = 0; j < 4; j++) {
            int nj = warp_n + 8 * j + l8;
            #pragma unroll
            for (int p = 0; p < 3; p++) {
                bf[p][j][0] = Bb(buf, p)[l4 * PR + nj];
                bf[p][j][1] = Bb(buf, p)[(l4 + 4) * PR + nj];
            }
        }
        #pragma unroll
        for (int i = 0; i < 4; i++) {
            int mi = warp_m + 16 * i + l8;
            unsigned av[3][4];
            #pragma unroll
            for (int p = 0; p < 3; p++) {
                av[p][0] = Ab(buf, p)[l4 * PR + mi];
                av[p][1] = Ab(buf, p)[l4 * PR + mi + 8];
                av[p][2] = Ab(buf, p)[(l4 + 4) * PR + mi];
                av[p][3] = Ab(buf, p)[(l4 + 4) * PR + mi + 8];
            }
            #pragma unroll
            for (int j = 0; j < 4; j++) {
                // per-tile temp accumulator: TC rounding confined to 6 adds,
                // long-K accumulation happens in fp32-RN FADDs below.
                float tmp[4] = {0.f, 0.f, 0.f, 0.f};
                mma_bf16(tmp, av[2], bf[0][j]);   // ~2^-18 terms first
                mma_bf16(tmp, av[0], bf[2][j]);
                mma_bf16(tmp, av[1], bf[1][j]);
                mma_bf16(tmp, av[1], bf[0][j]);   // ~2^-9
                mma_bf16(tmp, av[0], bf[1][j]);
                mma_bf16(tmp, av[0], bf[0][j]);   // main
                #pragma unroll
                for (int r = 0; r < 4; r++)
                    acc[i][j][r] += tmp[r];
            }
        }
    };

    // ---- pipeline ----
    gatherA(0); gatherB();
    storeA(0);  storeB(0);
    __syncthreads();
    #pragma unroll 1
    for (int kt = 0; kt < KT; kt++) {
        const int cur = kt & 1;
        if (kt + 1 < KT) { gatherA(kt + 1); gatherB(); }
        compute(cur);
        if (kt + 1 < KT) { storeA(cur ^ 1); storeB(cur ^ 1); }
        __syncthreads();
    }

    // ---- epilogue: c0,c1 at (row, 2*l4+{0,1}); c2,c3 at row+8 ----
    #pragma unroll
    for (int i = 0; i < 4; i++) {
        #pragma unroll
        for (int half = 0; half < 2; half++) {
            int m = m0 + warp_m + 16 * i + l8 + 8 * half;
            if (m >= COUT) continue;
            float bv = HASBIAS ? bias[m] : 0.f;
            #pragma unroll
            for (int j = 0; j < 4; j++) {
                int n2 = n0 + warp_n + 8 * j + 2 * l4;
                int b2 = n2 / OHW;
                int r2 = n2 - b2 * OHW;
                float v0 = acc[i][j][half * 2 + 0] + bv;
                float v1 = acc[i][j][half * 2 + 1] + bv;
                if (RELU) { v0 = fmaxf(v0, 0.f); v1 = fmaxf(v1, 0.f); }
                *(float2*)&out[((size_t)b2 * COUT + m) * OHW + r2] = make_float2(v0, v1);
            }
        }
    }
}

// dynamic smem bytes for conv3x3_bf: 2 bufs x 2 mats x 3 planes x 1088 words
#define CONV_SMEM (2 * 2 * 3 * (8 * 136) * 4)

// ---------------- dcn weight transpose: [o][g*16+c][k] -> [g][c*9+k][o] ----------------
__global__ void transpose_dcn_w(const float* __restrict__ dcn_w, float* __restrict__ wt)
{
    int e = blockIdx.x * 256 + threadIdx.x;
    if (e >= 4 * 144 * 64) return;
    int o   = e & 63;
    int gck = e >> 6;
    int g   = gck / 144;
    int ck  = gck - g * 144;
    int c   = ck / 9;
    int k   = ck - c * 9;
    wt[e] = dcn_w[((size_t)(o * 64 + g * 16 + c)) * 9 + k];
}

// ---------------- deformable conv (dg=4, Cg=16, K=3) ----------------
__global__ __launch_bounds__(128)
void deform_kernel(const float* __restrict__ sup,
                   const float* __restrict__ ow,
                   const float* __restrict__ wt,
                   float* __restrict__ out)
{
    __shared__ float s[144 * 32];
    const int t  = threadIdx.x;
    const int p0 = blockIdx.x * 32;
    const int og = t & 15;
    const int pg = t >> 4;

    float acc[4][4] = {};

    for (int g = 0; g < 4; g++) {
        if (g) __syncthreads();
        for (int tt = t; tt < 288; tt += 128) {
            int px = tt & 31;
            int k  = tt >> 5;
            int p  = p0 + px;
            int b  = p >> 14;
            int yx = p & 16383;
            int yy = yx >> 7;
            int xx = yx & 127;
            int ky = k / 3;
            int kx = k - ky * 3;
            int och = (g * 9 + k) * 2;
            const float* owb = ow + ((size_t)b * 73 + och) * 16384 + yx;
            float dy = owb[0];
            float dx = owb[16384];
            float py  = (float)(yy + ky - 1) + dy;
            float pxf = (float)(xx + kx - 1) + dx;
            float y0f = floorf(py), x0f = floorf(pxf);
            int   y0  = (int)y0f,  x0  = (int)x0f;
            float wy1 = py  - y0f, wx1 = pxf - x0f;
            float wy0 = 1.f - wy1, wx0 = 1.f - wx1;
            bool vy0 = (unsigned)y0       < 128u;
            bool vy1 = (unsigned)(y0 + 1) < 128u;
            bool vx0 = (unsigned)x0       < 128u;
            bool vx1 = (unsigned)(x0 + 1) < 128u;
            float w00 = (vy0 && vx0) ? wy0 * wx0 : 0.f;
            float w01 = (vy0 && vx1) ? wy0 * wx1 : 0.f;
            float w10 = (vy1 && vx0) ? wy1 * wx0 : 0.f;
            float w11 = (vy1 && vx1) ? wy1 * wx1 : 0.f;
            int yc0 = min(max(y0, 0), 127);
            int yc1 = min(max(y0 + 1, 0), 127);
            int xc0 = min(max(x0, 0), 127);
            int xc1 = min(max(x0 + 1, 0), 127);
            const float* fb = sup + ((size_t)b * 64 + g * 16) * 16384;
            int i00 = yc0 * 128 + xc0, i01 = yc0 * 128 + xc1;
            int i10 = yc1 * 128 + xc0, i11 = yc1 * 128 + xc1;
            #pragma unroll
            for (int c = 0; c < 16; c++) {
                const float* f = fb + c * 16384;
                float v = w00 * f[i00] + w01 * f[i01] + w10 * f[i10] + w11 * f[i11];
                s[(c * 9 + k) * 32 + px] = v;
            }
        }
        __syncthreads();
        const float* wg = wt + g * 144 * 64;
        #pragma unroll 4
        for (int ck = 0; ck < 144; ck++) {
            float4 v4 = *(const float4*)&s[ck * 32 + pg * 4];
            float4 w4 = __ldg((const float4*)(wg + ck * 64 + og * 4));
            float v[4]  = {v4.x, v4.y, v4.z, v4.w};
            float wv[4] = {w4.x, w4.y, w4.z, w4.w};
            #pragma unroll
            for (int i = 0; i < 4; i++)
                #pragma unroll
                for (int j = 0; j < 4; j++)
                    acc[i][j] = fmaf(v[i], wv[j], acc[i][j]);
        }
    }

    #pragma unroll
    for (int i = 0; i < 4; i++) {
        int p  = p0 + pg * 4 + i;
        int b  = p >> 14;
        int yx = p & 16383;
        #pragma unroll
        for (int j = 0; j < 4; j++) {
            int o = og * 4 + j;
            out[((size_t)b * 64 + o) * 16384 + yx] = acc[i][j];
        }
    }
}

// ---------------- weight channel: relu(ow[:,72]) ----------------
__global__ void weight_relu_kernel(const float* __restrict__ ow, float* __restrict__ out2)
{
    int i  = blockIdx.x * 256 + threadIdx.x;
    int b  = i >> 14;
    int yx = i & 16383;
    out2[i] = fmaxf(ow[((size_t)b * 73 + 72) * 16384 + yx], 0.f);
}

// ---------------- launch ----------------
extern "C" void kernel_launch(void* const* d_in, const int* in_sizes, int n_in,
                              void* d_out, int out_size)
{
    const float* cur    = (const float*)d_in[0];
    const float* sup    = (const float*)d_in[1];
    const float* off_w1 = (const float*)d_in[3];
    const float* off_w2 = (const float*)d_in[4];
    const float* off_w3 = (const float*)d_in[5];
    const float* lat_w  = (const float*)d_in[6];
    const float* lat_b  = (const float*)d_in[7];
    const float* pred_w = (const float*)d_in[8];
    const float* pred_b = (const float*)d_in[9];
    const float* dcn_w  = (const float*)d_in[10];
    float* out = (float*)d_out;

    float *c1, *c2, *c3, *lat, *owb, *wtb, *wT;
    cudaGetSymbolAddress((void**)&c1,  g_c1);
    cudaGetSymbolAddress((void**)&c2,  g_c2);
    cudaGetSymbolAddress((void**)&c3,  g_c3);
    cudaGetSymbolAddress((void**)&lat, g_lat);
    cudaGetSymbolAddress((void**)&owb, g_ow);
    cudaGetSymbolAddress((void**)&wtb, g_wt);
    cudaGetSymbolAddress((void**)&wT,  g_wT);

    // opt-in to >48KB dynamic smem for each conv instantiation (idempotent)
    cudaFuncSetAttribute(conv3x3_bf<1,128,256,256,1,128,128,false,false>,
                         cudaFuncAttributeMaxDynamicSharedMemorySize, CONV_SMEM);
    cudaFuncSetAttribute(conv3x3_bf<0,256,128,128,2,64,64,false,false>,
                         cudaFuncAttributeMaxDynamicSharedMemorySize, CONV_SMEM);
    cudaFuncSetAttribute(conv3x3_bf<0,128,128,128,2,32,32,false,false>,
                         cudaFuncAttributeMaxDynamicSharedMemorySize, CONV_SMEM);
    cudaFuncSetAttribute(conv3x3_bf<2,512,256,256,1,128,128,true,true>,
                         cudaFuncAttributeMaxDynamicSharedMemorySize, CONV_SMEM);
    cudaFuncSetAttribute(conv3x3_bf<0,256,73,128,1,128,128,false,true>,
                         cudaFuncAttributeMaxDynamicSharedMemorySize, CONV_SMEM);

    // weight prep (transpose + pad, fp32)
    prep_w<<<(1152*256 + 255)/256, 256>>>(off_w1, wT + WT_C1,  1152, 256, 256);
    prep_w<<<(2304*128 + 255)/256, 256>>>(off_w2, wT + WT_C2,  2304, 128, 128);
    prep_w<<<(1152*128 + 255)/256, 256>>>(off_w3, wT + WT_C3,  1152, 128, 128);
    prep_w<<<(4608*256 + 255)/256, 256>>>(lat_w,  wT + WT_LAT, 4608, 256, 256);
    prep_w<<<(2304*128 + 255)/256, 256>>>(pred_w, wT + WT_PRED,2304,  73, 128);
    transpose_dcn_w<<<144, 256>>>(dcn_w, wtb);

    // conv1: concat(cur,sup) -> c1 [4,256,128,128]
    conv3x3_bf<1,128,256,256,1,128,128,false,false>
        <<<dim3(512, 2), 256, CONV_SMEM>>>(cur, sup, nullptr, wT + WT_C1, nullptr, c1);
    // conv2: c1 -> c2 [4,128,64,64], stride 2
    conv3x3_bf<0,256,128,128,2,64,64,false,false>
        <<<dim3(128, 1), 256, CONV_SMEM>>>(c1, nullptr, nullptr, wT + WT_C2, nullptr, c2);
    // conv3: c2 -> c3 [4,128,32,32], stride 2
    conv3x3_bf<0,128,128,128,2,32,32,false,false>
        <<<dim3(32, 1), 256, CONV_SMEM>>>(c2, nullptr, nullptr, wT + WT_C3, nullptr, c3);
    // lat: relu-concat(c1, up2(c2), up4(c3)) -> relu(conv+bias)
    conv3x3_bf<2,512,256,256,1,128,128,true,true>
        <<<dim3(512, 2), 256, CONV_SMEM>>>(c1, c2, c3, wT + WT_LAT, lat_b, lat);
    // pred: lat -> ow [4,73,128,128]
    conv3x3_bf<0,256,73,128,1,128,128,false,true>
        <<<dim3(512, 1), 256, CONV_SMEM>>>(lat, nullptr, nullptr, wT + WT_PRED, pred_b, owb);

    deform_kernel<<<2048, 128>>>(sup, owb, wtb, out);
    weight_relu_kernel<<<256, 256>>>(owb, out + 4 * 64 * 128 * 128);
}